// round 6
// baseline (speedup 1.0000x reference)
#include <cuda_runtime.h>
#include <cuda_fp16.h>
#include <cstdint>

// ---------------- problem dims ----------------
#define TT 2048
#define KD 2048
#define ID 1024
#define NE 8
#define GSZ 64
#define BM 128
#define MAXT 56
#define ROWS_CAP 7168

#define GU_SMEM 69632
#define DN_SMEM 69632

__device__ __constant__ float c_lut[16] = {
    0.0f, 0.5f, 1.0f, 1.5f, 2.0f, 3.0f, 4.0f, 6.0f,
   -0.0f,-0.5f,-1.0f,-1.5f,-2.0f,-3.0f,-4.0f,-6.0f };

// ---------------- scratch ----------------
__device__ int   g_tok[ROWS_CAP];
__device__ float g_w[ROWS_CAP];
__device__ int   g_tile_e[MAXT];
__device__ int   g_tile_b[MAXT];
__device__ int   g_ntiles;
__device__ int   g_rowof[TT * 3];
__device__ __half g_x16[(size_t)TT * KD];
__device__ __half g_a16[(size_t)ROWS_CAP * ID];
__device__ float  g_y[(size_t)ROWS_CAP * KD];

// ---------------- helpers ----------------
static __device__ __forceinline__ uint32_t swz128(uint32_t o) { return o ^ ((o >> 3) & 0x70); }
static __device__ __forceinline__ uint32_t smem_u32(const void* p) {
    uint32_t a;
    asm("{ .reg .u64 t; cvta.to.shared.u64 t, %1; cvt.u32.u64 %0, t; }" : "=r"(a) : "l"(p));
    return a;
}
static __device__ __forceinline__ void ldmx4(uint32_t* r, uint32_t addr) {
    asm volatile("ldmatrix.sync.aligned.m8n8.x4.shared.b16 {%0,%1,%2,%3}, [%4];"
        : "=r"(r[0]), "=r"(r[1]), "=r"(r[2]), "=r"(r[3]) : "r"(addr));
}
static __device__ __forceinline__ void mma16816(float* d, const uint32_t* a,
                                                uint32_t b0, uint32_t b1, const float* c) {
    asm volatile(
        "mma.sync.aligned.m16n8k16.row.col.f32.f16.f16.f32 "
        "{%0,%1,%2,%3},{%4,%5,%6,%7},{%8,%9},{%10,%11,%12,%13};"
        : "=f"(d[0]), "=f"(d[1]), "=f"(d[2]), "=f"(d[3])
        : "r"(a[0]), "r"(a[1]), "r"(a[2]), "r"(a[3]), "r"(b0), "r"(b1),
          "f"(c[0]), "f"(c[1]), "f"(c[2]), "f"(c[3]));
}
static __device__ __forceinline__ void cpasync16(uint32_t dst, const void* src, int srcsize) {
    asm volatile("cp.async.cg.shared.global [%0], [%1], 16, %2;"
                 :: "r"(dst), "l"(src), "r"(srcsize));
}
#define CP_COMMIT asm volatile("cp.async.commit_group;" ::: "memory")
#define CP_WAIT0  asm volatile("cp.async.wait_group 0;" ::: "memory")

static __device__ __forceinline__ uint32_t pkh2(float a, float b) {
    __half2 t = __floats2half2_rn(a, b);
    return *reinterpret_cast<uint32_t*>(&t);
}
static __device__ __forceinline__ float silu_f(float g) { return g / (1.0f + __expf(-g)); }

// ---------------------------------------------------------------------------
// routing
// ---------------------------------------------------------------------------
__global__ void k_route(const int* __restrict__ eids, const float* __restrict__ probs)
{
    __shared__ int cnt[NE];
    __shared__ int offs[NE];
    __shared__ int baseE;
    int tid = threadIdx.x;
    if (tid < NE) cnt[tid] = 0;
    __syncthreads();
    for (int i = tid; i < TT * 2; i += blockDim.x) atomicAdd(&cnt[eids[i]], 1);
    __syncthreads();
    if (tid == 0) {
        int b = 0, tile = 0;
        for (int e = 0; e < NE; e++) {
            offs[e] = b;
            int nt = (cnt[e] + BM - 1) / BM;
            for (int j = 0; j < nt; j++) { g_tile_e[tile] = e; g_tile_b[tile] = b + j * BM; tile++; }
            b += nt * BM;
        }
        baseE = b;
        for (int j = 0; j < TT / BM; j++) { g_tile_e[tile] = NE; g_tile_b[tile] = b + j * BM; tile++; }
        g_ntiles = tile;
    }
    __syncthreads();
    for (int i = tid; i < ROWS_CAP; i += blockDim.x) { g_tok[i] = -1; g_w[i] = 0.0f; }
    __syncthreads();
    for (int i = tid; i < TT * 2; i += blockDim.x) {
        int e = eids[i];
        int pos = atomicAdd(&offs[e], 1);
        int t = i >> 1;
        g_tok[pos] = t;
        g_w[pos] = probs[i];
        g_rowof[t * 3 + (i & 1)] = pos;
    }
    int bs = baseE;
    for (int t = tid; t < TT; t += blockDim.x) {
        g_tok[bs + t] = t;
        g_w[bs + t] = 1.0f;
        g_rowof[t * 3 + 2] = bs + t;
    }
}

// ---------------------------------------------------------------------------
// convert x -> fp16
// ---------------------------------------------------------------------------
__global__ __launch_bounds__(256) void k_cvtx(const float* __restrict__ x)
{
    int idx = blockIdx.x * blockDim.x + threadIdx.x;   // over TT*KD/4
    float4 v = ((const float4*)x)[idx];
    uint2 o = make_uint2(pkh2(v.x, v.y), pkh2(v.z, v.w));
    ((uint2*)g_x16)[idx] = o;
}

// ---------------------------------------------------------------------------
// gate_up: block = 128 rows x (64 gate + 64 up cols). grid (MAXT, ID/64).
// smem: tblf 0..2KB (float2/byte), toks 2048..; A @4096 (2x16KB); B @36864 (2x16KB).
// B is dequantized WITH the group scale folded in (fp32 mul, rn to fp16).
// ---------------------------------------------------------------------------
__global__ __launch_bounds__(256, 2)
void k_gu(const int* __restrict__ gup, const float* __restrict__ gus,
          const int* __restrict__ sgup, const float* __restrict__ sgus)
{
    extern __shared__ __align__(16) char sm[];
    int tile = blockIdx.x;
    if (tile >= g_ntiles) return;
    int e = g_tile_e[tile], rbase = g_tile_b[tile];
    int n0 = blockIdx.y * 64;
    const int* wp; const float* sp;
    if (e < NE) { wp = gup + (size_t)e * (KD / 8) * (2 * ID); sp = gus + (size_t)e * (KD / GSZ) * (2 * ID); }
    else        { wp = sgup; sp = sgus; }

    float2* tblf = (float2*)sm;
    int* toks = (int*)(sm + 2048);
    uint32_t smb = smem_u32(sm);
    const int tid = threadIdx.x;

    tblf[tid] = make_float2(c_lut[tid & 15], c_lut[(tid >> 4) & 15]);
    if (tid < 128) toks[tid] = g_tok[rbase + tid];
    __syncthreads();

    // A cp.async geometry: 128 rows x 128B, 1024 chunks, 4 per thread
    int aoff[4]; uint32_t aswz[4];
    #pragma unroll
    for (int s = 0; s < 4; s++) {
        int idx = s * 256 + tid;
        int row = idx >> 3, q = idx & 7;
        int tok = toks[row];
        aoff[s] = (tok >= 0) ? (tok * (KD * 2) + q * 16) : -1;
        aswz[s] = swz128(row * 128 + q * 16);
    }
    // B geometry: 1024 words per chunk, 4 per thread
    int colw[4], jw4[4]; uint32_t dstB[4];
    #pragma unroll
    for (int i = 0; i < 4; i++) {
        int idx = i * 256 + tid;
        int n = idx >> 3, j = idx & 7;
        colw[i] = (n < 64) ? (n0 + n) : (ID + n0 + (n - 64));
        jw4[i] = j;
        dstB[i] = swz128(n * 128 + j * 16);
    }

    int lane = tid & 31, wid = tid >> 5;
    int wm = (wid & 3) * 32, ngw = wid >> 2;
    int rowA0 = (wm + (lane & 15)) * 128;
    int khA = lane >> 4;
    int rowBt[4];
    #pragma unroll
    for (int t = 0; t < 4; t++) {
        int base = (t < 2) ? (ngw * 32 + t * 16) : (64 + ngw * 32 + (t - 2) * 16);
        rowBt[t] = (base + (lane & 7) + ((lane >> 4) << 3)) * 128;
    }
    int khB = (lane >> 3) & 1;

    float accF[2][8][4];
    #pragma unroll
    for (int a = 0; a < 2; a++)
        #pragma unroll
        for (int b = 0; b < 8; b++)
            #pragma unroll
            for (int c = 0; c < 4; c++) accF[a][b][c] = 0.f;

    // prologue: B words + scales chunk0; cp.async A(0) -> buf0
    uint32_t bw[4]; float sw[4];
    #pragma unroll
    for (int i = 0; i < 4; i++) {
        bw[i] = (uint32_t)wp[(size_t)jw4[i] * (2 * ID) + colw[i]];
        sw[i] = sp[colw[i]];
    }
    #pragma unroll
    for (int s = 0; s < 4; s++) {
        int off = aoff[s];
        int sz = (off < 0) ? 0 : 16;
        int o = (off < 0) ? 0 : off;
        cpasync16(smb + 4096 + aswz[s], (const char*)g_x16 + o, sz);
    }
    CP_COMMIT;

    for (int kb = 0; kb < KD / 64; kb++) {
        int buf = kb & 1;
        // dequant-store B with scale folded in
        char* Bb = sm + 36864 + buf * 16384;
        #pragma unroll
        for (int i = 0; i < 4; i++) {
            uint32_t w = bw[i];
            float s = sw[i];
            float2 t0 = tblf[w & 255];
            float2 t1 = tblf[(w >> 8) & 255];
            float2 t2 = tblf[(w >> 16) & 255];
            float2 t3 = tblf[w >> 24];
            uint4 v;
            v.x = pkh2(t0.x * s, t0.y * s);
            v.y = pkh2(t1.x * s, t1.y * s);
            v.z = pkh2(t2.x * s, t2.y * s);
            v.w = pkh2(t3.x * s, t3.y * s);
            *(uint4*)(Bb + dstB[i]) = v;
        }
        CP_WAIT0;
        __syncthreads();
        if (kb + 1 < KD / 64) {
            int nb = buf ^ 1;
            #pragma unroll
            for (int s = 0; s < 4; s++) {
                int off = aoff[s];
                int sz = (off < 0) ? 0 : 16;
                int o = (off < 0) ? 0 : off + (kb + 1) * 128;
                cpasync16(smb + 4096 + nb * 16384 + aswz[s], (const char*)g_x16 + o, sz);
            }
            CP_COMMIT;
            #pragma unroll
            for (int i = 0; i < 4; i++) {
                bw[i] = (uint32_t)wp[(size_t)((kb + 1) * 8 + jw4[i]) * (2 * ID) + colw[i]];
                sw[i] = sp[(size_t)(kb + 1) * (2 * ID) + colw[i]];
            }
        }
        // MMA on current buffer (accumulate directly into accF)
        uint32_t Ab = smb + 4096 + buf * 16384;
        uint32_t Bba = smb + 36864 + buf * 16384;
        #pragma unroll
        for (int ks = 0; ks < 4; ks++) {
            uint32_t bfr[4][4];
            #pragma unroll
            for (int t = 0; t < 4; t++)
                ldmx4(bfr[t], Bba + swz128(rowBt[t] + (ks * 2 + khB) * 16));
            #pragma unroll
            for (int mf = 0; mf < 2; mf++) {
                uint32_t a[4];
                ldmx4(a, Ab + swz128(rowA0 + mf * 2048 + (ks * 2 + khA) * 16));
                #pragma unroll
                for (int nf = 0; nf < 8; nf++)
                    mma16816(accF[mf][nf], a,
                             bfr[nf >> 1][(nf & 1) * 2], bfr[nf >> 1][(nf & 1) * 2 + 1],
                             accF[mf][nf]);
            }
        }
    }

    // epilogue: silu(gate)*up -> fp16
    #pragma unroll
    for (int mf = 0; mf < 2; mf++) {
        int r0 = rbase + wm + mf * 16 + (lane >> 2);
        #pragma unroll
        for (int nf = 0; nf < 4; nf++) {
            int icol = n0 + ngw * 32 + nf * 8 + (lane & 3) * 2;
            float* G = accF[mf][nf];
            float* U = accF[mf][nf + 4];
            float a0 = silu_f(G[0]) * U[0];
            float a1 = silu_f(G[1]) * U[1];
            float a2 = silu_f(G[2]) * U[2];
            float a3 = silu_f(G[3]) * U[3];
            *(uint32_t*)(g_a16 + (size_t)r0 * ID + icol)       = pkh2(a0, a1);
            *(uint32_t*)(g_a16 + (size_t)(r0 + 8) * ID + icol) = pkh2(a2, a3);
        }
    }
}

// ---------------------------------------------------------------------------
// down: block = 128 rows x 128 out cols. grid (MAXT, KD/128).
// Same skeleton as k_gu; epilogue applies routing weight, writes fp32 y.
// ---------------------------------------------------------------------------
__global__ __launch_bounds__(256, 2)
void k_dn(const int* __restrict__ dwp, const float* __restrict__ dws,
          const int* __restrict__ sdwp, const float* __restrict__ sdws)
{
    extern __shared__ __align__(16) char sm[];
    int tile = blockIdx.x;
    if (tile >= g_ntiles) return;
    int e = g_tile_e[tile], rbase = g_tile_b[tile];
    int n0 = blockIdx.y * 128;
    const int* wp; const float* sp;
    if (e < NE) { wp = dwp + (size_t)e * (ID / 8) * KD; sp = dws + (size_t)e * (ID / GSZ) * KD; }
    else        { wp = sdwp; sp = sdws; }

    float2* tblf = (float2*)sm;
    uint32_t smb = smem_u32(sm);
    const int tid = threadIdx.x;

    tblf[tid] = make_float2(c_lut[tid & 15], c_lut[(tid >> 4) & 15]);
    __syncthreads();

    int aoff[4]; uint32_t aswz[4];
    #pragma unroll
    for (int s = 0; s < 4; s++) {
        int idx = s * 256 + tid;
        int row = idx >> 3, q = idx & 7;
        aoff[s] = (rbase + row) * (ID * 2) + q * 16;
        aswz[s] = swz128(row * 128 + q * 16);
    }
    int colw[4], jw4[4]; uint32_t dstB[4];
    #pragma unroll
    for (int i = 0; i < 4; i++) {
        int idx = i * 256 + tid;
        int n = idx >> 3, j = idx & 7;
        colw[i] = n0 + n;
        jw4[i] = j;
        dstB[i] = swz128(n * 128 + j * 16);
    }

    int lane = tid & 31, wid = tid >> 5;
    int wm = (wid & 3) * 32, ngw = wid >> 2;
    int rowA0 = (wm + (lane & 15)) * 128;
    int khA = lane >> 4;
    int rowBt[4];
    #pragma unroll
    for (int t = 0; t < 4; t++) {
        int base = (t < 2) ? (ngw * 32 + t * 16) : (64 + ngw * 32 + (t - 2) * 16);
        rowBt[t] = (base + (lane & 7) + ((lane >> 4) << 3)) * 128;
    }
    int khB = (lane >> 3) & 1;

    float accF[2][8][4];
    #pragma unroll
    for (int a = 0; a < 2; a++)
        #pragma unroll
        for (int b = 0; b < 8; b++)
            #pragma unroll
            for (int c = 0; c < 4; c++) accF[a][b][c] = 0.f;

    uint32_t bw[4]; float sw[4];
    #pragma unroll
    for (int i = 0; i < 4; i++) {
        bw[i] = (uint32_t)wp[(size_t)jw4[i] * KD + colw[i]];
        sw[i] = sp[colw[i]];
    }
    #pragma unroll
    for (int s = 0; s < 4; s++)
        cpasync16(smb + 4096 + aswz[s], (const char*)g_a16 + aoff[s], 16);
    CP_COMMIT;

    for (int ib = 0; ib < ID / 64; ib++) {
        int buf = ib & 1;
        char* Bb = sm + 36864 + buf * 16384;
        #pragma unroll
        for (int i = 0; i < 4; i++) {
            uint32_t w = bw[i];
            float s = sw[i];
            float2 t0 = tblf[w & 255];
            float2 t1 = tblf[(w >> 8) & 255];
            float2 t2 = tblf[(w >> 16) & 255];
            float2 t3 = tblf[w >> 24];
            uint4 v;
            v.x = pkh2(t0.x * s, t0.y * s);
            v.y = pkh2(t1.x * s, t1.y * s);
            v.z = pkh2(t2.x * s, t2.y * s);
            v.w = pkh2(t3.x * s, t3.y * s);
            *(uint4*)(Bb + dstB[i]) = v;
        }
        CP_WAIT0;
        __syncthreads();
        if (ib + 1 < ID / 64) {
            int nb = buf ^ 1;
            #pragma unroll
            for (int s = 0; s < 4; s++) {
                int o = aoff[s] + (ib + 1) * 128;
                cpasync16(smb + 4096 + nb * 16384 + aswz[s], (const char*)g_a16 + o, 16);
            }
            CP_COMMIT;
            #pragma unroll
            for (int i = 0; i < 4; i++) {
                bw[i] = (uint32_t)wp[(size_t)((ib + 1) * 8 + jw4[i]) * KD + colw[i]];
                sw[i] = sp[(size_t)(ib + 1) * KD + colw[i]];
            }
        }
        uint32_t Ab = smb + 4096 + buf * 16384;
        uint32_t Bba = smb + 36864 + buf * 16384;
        #pragma unroll
        for (int ks = 0; ks < 4; ks++) {
            uint32_t bfr[4][4];
            #pragma unroll
            for (int t = 0; t < 4; t++)
                ldmx4(bfr[t], Bba + swz128(rowBt[t] + (ks * 2 + khB) * 16));
            #pragma unroll
            for (int mf = 0; mf < 2; mf++) {
                uint32_t a[4];
                ldmx4(a, Ab + swz128(rowA0 + mf * 2048 + (ks * 2 + khA) * 16));
                #pragma unroll
                for (int nf = 0; nf < 8; nf++)
                    mma16816(accF[mf][nf], a,
                             bfr[nf >> 1][(nf & 1) * 2], bfr[nf >> 1][(nf & 1) * 2 + 1],
                             accF[mf][nf]);
            }
        }
    }

    // epilogue: apply routing weight, write fp32 y
    #pragma unroll
    for (int mf = 0; mf < 2; mf++) {
        int r0 = rbase + wm + mf * 16 + (lane >> 2);
        float w0 = g_w[r0], w1 = g_w[r0 + 8];
        #pragma unroll
        for (int nf = 0; nf < 8; nf++) {
            int col = n0 + ((nf < 4) ? 0 : 64) + ngw * 32 + (nf & 3) * 8 + (lane & 3) * 2;
            float2 o0, o1;
            o0.x = accF[mf][nf][0] * w0; o0.y = accF[mf][nf][1] * w0;
            o1.x = accF[mf][nf][2] * w1; o1.y = accF[mf][nf][3] * w1;
            *(float2*)(g_y + (size_t)r0 * KD + col)       = o0;
            *(float2*)(g_y + (size_t)(r0 + 8) * KD + col) = o1;
        }
    }
}

// ---------------------------------------------------------------------------
__global__ __launch_bounds__(256) void k_combine(float* __restrict__ out)
{
    int idx = blockIdx.x * blockDim.x + threadIdx.x;
    int t = idx / (KD / 4);
    int kq = (idx % (KD / 4)) * 4;
    int r0 = g_rowof[t * 3 + 0];
    int r1 = g_rowof[t * 3 + 1];
    int r2 = g_rowof[t * 3 + 2];
    float4 a = *(const float4*)&g_y[(size_t)r0 * KD + kq];
    float4 b = *(const float4*)&g_y[(size_t)r1 * KD + kq];
    float4 c = *(const float4*)&g_y[(size_t)r2 * KD + kq];
    float4 o;
    o.x = a.x + b.x + c.x;
    o.y = a.y + b.y + c.y;
    o.z = a.z + b.z + c.z;
    o.w = a.w + b.w + c.w;
    *(float4*)&out[(size_t)t * KD + kq] = o;
}

// ---------------------------------------------------------------------------
extern "C" void kernel_launch(void* const* d_in, const int* in_sizes, int n_in,
                              void* d_out, int out_size)
{
    const float* x     = (const float*)d_in[0];
    const int*   gup   = (const int*)  d_in[1];
    const float* gus   = (const float*)d_in[2];
    const int*   dwp   = (const int*)  d_in[3];
    const float* dws   = (const float*)d_in[4];
    const int*   sgup  = (const int*)  d_in[5];
    const float* sgus  = (const float*)d_in[6];
    const int*   sdwp  = (const int*)  d_in[7];
    const float* sdws  = (const float*)d_in[8];
    const int*   eids  = (const int*)  d_in[9];
    const float* probs = (const float*)d_in[10];
    float* out = (float*)d_out;

    cudaFuncSetAttribute(k_gu, cudaFuncAttributeMaxDynamicSharedMemorySize, GU_SMEM);
    cudaFuncSetAttribute(k_dn, cudaFuncAttributeMaxDynamicSharedMemorySize, DN_SMEM);

    k_route<<<1, 256>>>(eids, probs);
    k_cvtx<<<(TT * KD / 4) / 256, 256>>>(x);
    k_gu<<<dim3(MAXT, ID / 64), 256, GU_SMEM>>>(gup, gus, sgup, sgus);
    k_dn<<<dim3(MAXT, KD / 128), 256, DN_SMEM>>>(dwp, dws, sdwp, sdws);
    k_combine<<<(TT * KD / 4) / 256, 256>>>(out);
}

// round 7
// speedup vs baseline: 1.1189x; 1.1189x over previous
#include <cuda_runtime.h>
#include <cuda_fp16.h>
#include <cstdint>

// ---------------- problem dims ----------------
#define TT 2048
#define KD 2048
#define ID 1024
#define NE 8
#define GSZ 64
#define BM 128
#define MAXT 56
#define ROWS_CAP 7168

#define GU_SMEM 69632
#define DN_SMEM 69632

__device__ __constant__ float c_lut[16] = {
    0.0f, 0.5f, 1.0f, 1.5f, 2.0f, 3.0f, 4.0f, 6.0f,
   -0.0f,-0.5f,-1.0f,-1.5f,-2.0f,-3.0f,-4.0f,-6.0f };

// ---------------- scratch ----------------
__device__ int   g_tok[ROWS_CAP];
__device__ float g_w[ROWS_CAP];
__device__ int   g_tile_e[MAXT];
__device__ int   g_tile_b[MAXT];
__device__ int   g_ntiles;
__device__ int   g_rowof[TT * 3];
__device__ __half g_x16[(size_t)TT * KD];
__device__ __half g_a16[(size_t)ROWS_CAP * ID];
__device__ float  g_y[(size_t)ROWS_CAP * KD];

// ---------------- helpers ----------------
static __device__ __forceinline__ uint32_t swz128(uint32_t o) { return o ^ ((o >> 3) & 0x70); }
static __device__ __forceinline__ uint32_t smem_u32(const void* p) {
    uint32_t a;
    asm("{ .reg .u64 t; cvta.to.shared.u64 t, %1; cvt.u32.u64 %0, t; }" : "=r"(a) : "l"(p));
    return a;
}
static __device__ __forceinline__ void ldmx4(uint32_t* r, uint32_t addr) {
    asm volatile("ldmatrix.sync.aligned.m8n8.x4.shared.b16 {%0,%1,%2,%3}, [%4];"
        : "=r"(r[0]), "=r"(r[1]), "=r"(r[2]), "=r"(r[3]) : "r"(addr));
}
static __device__ __forceinline__ void mma16816(float* d, const uint32_t* a,
                                                uint32_t b0, uint32_t b1, const float* c) {
    asm volatile(
        "mma.sync.aligned.m16n8k16.row.col.f32.f16.f16.f32 "
        "{%0,%1,%2,%3},{%4,%5,%6,%7},{%8,%9},{%10,%11,%12,%13};"
        : "=f"(d[0]), "=f"(d[1]), "=f"(d[2]), "=f"(d[3])
        : "r"(a[0]), "r"(a[1]), "r"(a[2]), "r"(a[3]), "r"(b0), "r"(b1),
          "f"(c[0]), "f"(c[1]), "f"(c[2]), "f"(c[3]));
}
static __device__ __forceinline__ void cpasync16(uint32_t dst, const void* src, int srcsize) {
    asm volatile("cp.async.cg.shared.global [%0], [%1], 16, %2;"
                 :: "r"(dst), "l"(src), "r"(srcsize));
}
#define CP_COMMIT asm volatile("cp.async.commit_group;" ::: "memory")
#define CP_WAIT0  asm volatile("cp.async.wait_group 0;" ::: "memory")

static __device__ __forceinline__ uint32_t pkh2(float a, float b) {
    __half2 t = __floats2half2_rn(a, b);
    return *reinterpret_cast<uint32_t*>(&t);
}
static __device__ __forceinline__ float silu_f(float g) { return g / (1.0f + __expf(-g)); }

// ---------------------------------------------------------------------------
// routing
// ---------------------------------------------------------------------------
__global__ void k_route(const int* __restrict__ eids, const float* __restrict__ probs)
{
    __shared__ int cnt[NE];
    __shared__ int offs[NE];
    __shared__ int baseE;
    int tid = threadIdx.x;
    if (tid < NE) cnt[tid] = 0;
    __syncthreads();
    for (int i = tid; i < TT * 2; i += blockDim.x) atomicAdd(&cnt[eids[i]], 1);
    __syncthreads();
    if (tid == 0) {
        int b = 0, tile = 0;
        for (int e = 0; e < NE; e++) {
            offs[e] = b;
            int nt = (cnt[e] + BM - 1) / BM;
            for (int j = 0; j < nt; j++) { g_tile_e[tile] = e; g_tile_b[tile] = b + j * BM; tile++; }
            b += nt * BM;
        }
        baseE = b;
        for (int j = 0; j < TT / BM; j++) { g_tile_e[tile] = NE; g_tile_b[tile] = b + j * BM; tile++; }
        g_ntiles = tile;
    }
    __syncthreads();
    for (int i = tid; i < ROWS_CAP; i += blockDim.x) { g_tok[i] = -1; g_w[i] = 0.0f; }
    __syncthreads();
    for (int i = tid; i < TT * 2; i += blockDim.x) {
        int e = eids[i];
        int pos = atomicAdd(&offs[e], 1);
        int t = i >> 1;
        g_tok[pos] = t;
        g_w[pos] = probs[i];
        g_rowof[t * 3 + (i & 1)] = pos;
    }
    int bs = baseE;
    for (int t = tid; t < TT; t += blockDim.x) {
        g_tok[bs + t] = t;
        g_w[bs + t] = 1.0f;
        g_rowof[t * 3 + 2] = bs + t;
    }
}

// ---------------------------------------------------------------------------
// convert x -> fp16
// ---------------------------------------------------------------------------
__global__ __launch_bounds__(256) void k_cvtx(const float* __restrict__ x)
{
    int idx = blockIdx.x * blockDim.x + threadIdx.x;   // over TT*KD/4
    float4 v = ((const float4*)x)[idx];
    uint2 o = make_uint2(pkh2(v.x, v.y), pkh2(v.z, v.w));
    ((uint2*)g_x16)[idx] = o;
}

// ---------------------------------------------------------------------------
// gate_up: 128 threads, 4 warps (2m x 2n), warp tile 64 rows x (32g + 32u).
// Block: 128 rows x (64 gate + 64 up). grid (MAXT, ID/64).
// smem: tblf 0..2KB; toks 2048..; A @4096 (2x16KB); B @36864 (2x16KB).
// ---------------------------------------------------------------------------
__global__ __launch_bounds__(128, 2)
void k_gu(const int* __restrict__ gup, const float* __restrict__ gus,
          const int* __restrict__ sgup, const float* __restrict__ sgus)
{
    extern __shared__ __align__(16) char sm[];
    int tile = blockIdx.x;
    if (tile >= g_ntiles) return;
    int e = g_tile_e[tile], rbase = g_tile_b[tile];
    int n0 = blockIdx.y * 64;
    const int* wp; const float* sp;
    if (e < NE) { wp = gup + (size_t)e * (KD / 8) * (2 * ID); sp = gus + (size_t)e * (KD / GSZ) * (2 * ID); }
    else        { wp = sgup; sp = sgus; }

    float2* tblf = (float2*)sm;
    int* toks = (int*)(sm + 2048);
    uint32_t smb = smem_u32(sm);
    const int tid = threadIdx.x;

    tblf[tid]       = make_float2(c_lut[tid & 15], c_lut[(tid >> 4) & 15]);
    tblf[tid + 128] = make_float2(c_lut[(tid + 128) & 15], c_lut[((tid + 128) >> 4) & 15]);
    toks[tid] = g_tok[rbase + tid];
    __syncthreads();

    // A cp.async geometry: 1024 16B-chunks, 8 per thread
    int aoff[8]; uint32_t aswz[8];
    #pragma unroll
    for (int s = 0; s < 8; s++) {
        int idx = s * 128 + tid;
        int row = idx >> 3, q = idx & 7;
        int tok = toks[row];
        aoff[s] = (tok >= 0) ? (tok * (KD * 2) + q * 16) : -1;
        aswz[s] = swz128(row * 128 + q * 16);
    }

    int lane = tid & 31, wid = tid >> 5;
    int wm = (wid & 1) * 64;          // 64-row group
    int wn = (wid >> 1) * 32;         // 32-col group within gate (and within up)
    int rowA0 = (wm + (lane & 15)) * 128;
    int khA = lane >> 4;
    int rowBt[4];
    #pragma unroll
    for (int t = 0; t < 4; t++) {
        int base = (t < 2) ? (wn + t * 16) : (64 + wn + (t - 2) * 16);
        rowBt[t] = (base + (lane & 7) + ((lane >> 4) << 3)) * 128;
    }
    int khB = (lane >> 3) & 1;

    float accF[4][8][4];
    #pragma unroll
    for (int a = 0; a < 4; a++)
        #pragma unroll
        for (int b = 0; b < 8; b++)
            #pragma unroll
            for (int c = 0; c < 4; c++) accF[a][b][c] = 0.f;

    // prologue: B words + scales chunk0; cp.async A(0) -> buf0
    uint32_t bw[8]; float sw[8];
    #pragma unroll
    for (int i = 0; i < 8; i++) {
        int idx = i * 128 + tid;
        int n = idx >> 3, j = idx & 7;
        int col = (n < 64) ? (n0 + n) : (ID + n0 + (n - 64));
        bw[i] = (uint32_t)wp[(size_t)j * (2 * ID) + col];
        sw[i] = sp[col];
    }
    #pragma unroll
    for (int s = 0; s < 8; s++) {
        int off = aoff[s];
        int sz = (off < 0) ? 0 : 16;
        int o = (off < 0) ? 0 : off;
        cpasync16(smb + 4096 + aswz[s], (const char*)g_x16 + o, sz);
    }
    CP_COMMIT;

    for (int kb = 0; kb < KD / 64; kb++) {
        int buf = kb & 1;
        // dequant-store B with scale folded in
        char* Bb = sm + 36864 + buf * 16384;
        #pragma unroll
        for (int i = 0; i < 8; i++) {
            int idx = i * 128 + tid;
            int n = idx >> 3, j = idx & 7;
            uint32_t w = bw[i];
            float s = sw[i];
            float2 t0 = tblf[w & 255];
            float2 t1 = tblf[(w >> 8) & 255];
            float2 t2 = tblf[(w >> 16) & 255];
            float2 t3 = tblf[w >> 24];
            uint4 v;
            v.x = pkh2(t0.x * s, t0.y * s);
            v.y = pkh2(t1.x * s, t1.y * s);
            v.z = pkh2(t2.x * s, t2.y * s);
            v.w = pkh2(t3.x * s, t3.y * s);
            *(uint4*)(Bb + swz128(n * 128 + j * 16)) = v;
        }
        CP_WAIT0;
        __syncthreads();
        if (kb + 1 < KD / 64) {
            int nb = buf ^ 1;
            #pragma unroll
            for (int s = 0; s < 8; s++) {
                int off = aoff[s];
                int sz = (off < 0) ? 0 : 16;
                int o = (off < 0) ? 0 : off + (kb + 1) * 128;
                cpasync16(smb + 4096 + nb * 16384 + aswz[s], (const char*)g_x16 + o, sz);
            }
            CP_COMMIT;
            #pragma unroll
            for (int i = 0; i < 8; i++) {
                int idx = i * 128 + tid;
                int n = idx >> 3, j = idx & 7;
                int col = (n < 64) ? (n0 + n) : (ID + n0 + (n - 64));
                bw[i] = (uint32_t)wp[(size_t)((kb + 1) * 8 + j) * (2 * ID) + col];
                sw[i] = sp[(size_t)(kb + 1) * (2 * ID) + col];
            }
        }
        // MMA on current buffer
        uint32_t Ab = smb + 4096 + buf * 16384;
        uint32_t Bba = smb + 36864 + buf * 16384;
        #pragma unroll
        for (int ks = 0; ks < 4; ks++) {
            uint32_t bfr[4][4];
            #pragma unroll
            for (int t = 0; t < 4; t++)
                ldmx4(bfr[t], Bba + swz128(rowBt[t] + (ks * 2 + khB) * 16));
            #pragma unroll
            for (int mf = 0; mf < 4; mf++) {
                uint32_t a[4];
                ldmx4(a, Ab + swz128(rowA0 + mf * 2048 + (ks * 2 + khA) * 16));
                #pragma unroll
                for (int nf = 0; nf < 8; nf++)
                    mma16816(accF[mf][nf], a,
                             bfr[nf >> 1][(nf & 1) * 2], bfr[nf >> 1][(nf & 1) * 2 + 1],
                             accF[mf][nf]);
            }
        }
    }

    // epilogue: silu(gate)*up -> fp16 (nf 0-3 gate, 4-7 up)
    #pragma unroll
    for (int mf = 0; mf < 4; mf++) {
        int r0 = rbase + wm + mf * 16 + (lane >> 2);
        #pragma unroll
        for (int nf = 0; nf < 4; nf++) {
            int icol = n0 + wn + nf * 8 + (lane & 3) * 2;
            float* G = accF[mf][nf];
            float* U = accF[mf][nf + 4];
            float a0 = silu_f(G[0]) * U[0];
            float a1 = silu_f(G[1]) * U[1];
            float a2 = silu_f(G[2]) * U[2];
            float a3 = silu_f(G[3]) * U[3];
            *(uint32_t*)(g_a16 + (size_t)r0 * ID + icol)       = pkh2(a0, a1);
            *(uint32_t*)(g_a16 + (size_t)(r0 + 8) * ID + icol) = pkh2(a2, a3);
        }
    }
}

// ---------------------------------------------------------------------------
// down: 128 threads, 4 warps (2m x 2n), warp tile 64x64.
// Block: 128 rows x 128 out cols. grid (MAXT, KD/128).
// ---------------------------------------------------------------------------
__global__ __launch_bounds__(128, 2)
void k_dn(const int* __restrict__ dwp, const float* __restrict__ dws,
          const int* __restrict__ sdwp, const float* __restrict__ sdws)
{
    extern __shared__ __align__(16) char sm[];
    int tile = blockIdx.x;
    if (tile >= g_ntiles) return;
    int e = g_tile_e[tile], rbase = g_tile_b[tile];
    int n0 = blockIdx.y * 128;
    const int* wp; const float* sp;
    if (e < NE) { wp = dwp + (size_t)e * (ID / 8) * KD; sp = dws + (size_t)e * (ID / GSZ) * KD; }
    else        { wp = sdwp; sp = sdws; }

    float2* tblf = (float2*)sm;
    uint32_t smb = smem_u32(sm);
    const int tid = threadIdx.x;

    tblf[tid]       = make_float2(c_lut[tid & 15], c_lut[(tid >> 4) & 15]);
    tblf[tid + 128] = make_float2(c_lut[(tid + 128) & 15], c_lut[((tid + 128) >> 4) & 15]);
    __syncthreads();

    int aoff[8]; uint32_t aswz[8];
    #pragma unroll
    for (int s = 0; s < 8; s++) {
        int idx = s * 128 + tid;
        int row = idx >> 3, q = idx & 7;
        aoff[s] = (rbase + row) * (ID * 2) + q * 16;
        aswz[s] = swz128(row * 128 + q * 16);
    }

    int lane = tid & 31, wid = tid >> 5;
    int wm = (wid & 1) * 64;
    int wn = (wid >> 1) * 64;
    int rowA0 = (wm + (lane & 15)) * 128;
    int khA = lane >> 4;
    int rowBt[4];
    #pragma unroll
    for (int t = 0; t < 4; t++)
        rowBt[t] = (wn + t * 16 + (lane & 7) + ((lane >> 4) << 3)) * 128;
    int khB = (lane >> 3) & 1;

    float accF[4][8][4];
    #pragma unroll
    for (int a = 0; a < 4; a++)
        #pragma unroll
        for (int b = 0; b < 8; b++)
            #pragma unroll
            for (int c = 0; c < 4; c++) accF[a][b][c] = 0.f;

    uint32_t bw[8]; float sw[8];
    #pragma unroll
    for (int i = 0; i < 8; i++) {
        int idx = i * 128 + tid;
        int n = idx >> 3, j = idx & 7;
        bw[i] = (uint32_t)wp[(size_t)j * KD + n0 + n];
        sw[i] = sp[n0 + n];
    }
    #pragma unroll
    for (int s = 0; s < 8; s++)
        cpasync16(smb + 4096 + aswz[s], (const char*)g_a16 + aoff[s], 16);
    CP_COMMIT;

    for (int ib = 0; ib < ID / 64; ib++) {
        int buf = ib & 1;
        char* Bb = sm + 36864 + buf * 16384;
        #pragma unroll
        for (int i = 0; i < 8; i++) {
            int idx = i * 128 + tid;
            int n = idx >> 3, j = idx & 7;
            uint32_t w = bw[i];
            float s = sw[i];
            float2 t0 = tblf[w & 255];
            float2 t1 = tblf[(w >> 8) & 255];
            float2 t2 = tblf[(w >> 16) & 255];
            float2 t3 = tblf[w >> 24];
            uint4 v;
            v.x = pkh2(t0.x * s, t0.y * s);
            v.y = pkh2(t1.x * s, t1.y * s);
            v.z = pkh2(t2.x * s, t2.y * s);
            v.w = pkh2(t3.x * s, t3.y * s);
            *(uint4*)(Bb + swz128(n * 128 + j * 16)) = v;
        }
        CP_WAIT0;
        __syncthreads();
        if (ib + 1 < ID / 64) {
            int nb = buf ^ 1;
            #pragma unroll
            for (int s = 0; s < 8; s++) {
                int o = aoff[s] + (ib + 1) * 128;
                cpasync16(smb + 4096 + nb * 16384 + aswz[s], (const char*)g_a16 + o, 16);
            }
            CP_COMMIT;
            #pragma unroll
            for (int i = 0; i < 8; i++) {
                int idx = i * 128 + tid;
                int n = idx >> 3, j = idx & 7;
                bw[i] = (uint32_t)wp[(size_t)((ib + 1) * 8 + j) * KD + n0 + n];
                sw[i] = sp[(size_t)(ib + 1) * KD + n0 + n];
            }
        }
        uint32_t Ab = smb + 4096 + buf * 16384;
        uint32_t Bba = smb + 36864 + buf * 16384;
        #pragma unroll
        for (int ks = 0; ks < 4; ks++) {
            uint32_t bfr[4][4];
            #pragma unroll
            for (int t = 0; t < 4; t++)
                ldmx4(bfr[t], Bba + swz128(rowBt[t] + (ks * 2 + khB) * 16));
            #pragma unroll
            for (int mf = 0; mf < 4; mf++) {
                uint32_t a[4];
                ldmx4(a, Ab + swz128(rowA0 + mf * 2048 + (ks * 2 + khA) * 16));
                #pragma unroll
                for (int nf = 0; nf < 8; nf++)
                    mma16816(accF[mf][nf], a,
                             bfr[nf >> 1][(nf & 1) * 2], bfr[nf >> 1][(nf & 1) * 2 + 1],
                             accF[mf][nf]);
            }
        }
    }

    // epilogue: apply routing weight, write fp32 y
    #pragma unroll
    for (int mf = 0; mf < 4; mf++) {
        int r0 = rbase + wm + mf * 16 + (lane >> 2);
        float w0 = g_w[r0], w1 = g_w[r0 + 8];
        #pragma unroll
        for (int nf = 0; nf < 8; nf++) {
            int col = n0 + wn + nf * 8 + (lane & 3) * 2;
            float2 o0, o1;
            o0.x = accF[mf][nf][0] * w0; o0.y = accF[mf][nf][1] * w0;
            o1.x = accF[mf][nf][2] * w1; o1.y = accF[mf][nf][3] * w1;
            *(float2*)(g_y + (size_t)r0 * KD + col)       = o0;
            *(float2*)(g_y + (size_t)(r0 + 8) * KD + col) = o1;
        }
    }
}

// ---------------------------------------------------------------------------
__global__ __launch_bounds__(256) void k_combine(float* __restrict__ out)
{
    int idx = blockIdx.x * blockDim.x + threadIdx.x;
    int t = idx / (KD / 4);
    int kq = (idx % (KD / 4)) * 4;
    int r0 = g_rowof[t * 3 + 0];
    int r1 = g_rowof[t * 3 + 1];
    int r2 = g_rowof[t * 3 + 2];
    float4 a = *(const float4*)&g_y[(size_t)r0 * KD + kq];
    float4 b = *(const float4*)&g_y[(size_t)r1 * KD + kq];
    float4 c = *(const float4*)&g_y[(size_t)r2 * KD + kq];
    float4 o;
    o.x = a.x + b.x + c.x;
    o.y = a.y + b.y + c.y;
    o.z = a.z + b.z + c.z;
    o.w = a.w + b.w + c.w;
    *(float4*)&out[(size_t)t * KD + kq] = o;
}

// ---------------------------------------------------------------------------
extern "C" void kernel_launch(void* const* d_in, const int* in_sizes, int n_in,
                              void* d_out, int out_size)
{
    const float* x     = (const float*)d_in[0];
    const int*   gup   = (const int*)  d_in[1];
    const float* gus   = (const float*)d_in[2];
    const int*   dwp   = (const int*)  d_in[3];
    const float* dws   = (const float*)d_in[4];
    const int*   sgup  = (const int*)  d_in[5];
    const float* sgus  = (const float*)d_in[6];
    const int*   sdwp  = (const int*)  d_in[7];
    const float* sdws  = (const float*)d_in[8];
    const int*   eids  = (const int*)  d_in[9];
    const float* probs = (const float*)d_in[10];
    float* out = (float*)d_out;

    cudaFuncSetAttribute(k_gu, cudaFuncAttributeMaxDynamicSharedMemorySize, GU_SMEM);
    cudaFuncSetAttribute(k_dn, cudaFuncAttributeMaxDynamicSharedMemorySize, DN_SMEM);

    k_route<<<1, 256>>>(eids, probs);
    k_cvtx<<<(TT * KD / 4) / 256, 256>>>(x);
    k_gu<<<dim3(MAXT, ID / 64), 128, GU_SMEM>>>(gup, gus, sgup, sgus);
    k_dn<<<dim3(MAXT, KD / 128), 128, DN_SMEM>>>(dwp, dws, sdwp, sdws);
    k_combine<<<(TT * KD / 4) / 256, 256>>>(out);
}